// round 15
// baseline (speedup 1.0000x reference)
#include <cuda_runtime.h>
#include <cuda_bf16.h>
#include <cstdint>

// Problem constants (fixed shapes)
#define BB    8
#define VV    49152
#define FIN   64
#define FOUT  64
#define NNZ   393216
#define MM    (BB * VV)      // 393216 GEMM rows

// ---------------- device scratch (allocation-free) ----------------
__device__ float g_x1[(size_t)MM * 64];   // x1 = L @ x0, layout [B][V][64]
__device__ float g_xt[(size_t)MM * 64];   // t  = L @ x1, layout [B][V][64]
__device__ int   g_cnt[VV];               // invariant: zero at kernel_launch entry
__device__ int   g_rank[NNZ];             // per-edge rank within its row
__device__ int   g_rowptr[VV + 1];
__device__ int   g_agg[48];
__device__ int   g_flag[48];              // zeroed by k_count each call
__device__ int   g_colidx[NNZ];
__device__ float g_vals[NNZ];
// folded + transposed + bf16-split weights: 6 tiles [n=64][k=64]:
// tile 2s = hi(Wc_s^T), tile 2s+1 = lo(Wc_s^T)
__device__ __nv_bfloat16 g_wb[6 * 64 * 64];

// ================= warp MMA helpers (arch-agnostic, sm_80+) =================
__device__ __forceinline__ void mma_bf16(float* d, const uint32_t* a,
                                         uint32_t b0, uint32_t b1) {
    asm volatile(
        "mma.sync.aligned.m16n8k16.row.col.f32.bf16.bf16.f32 "
        "{%0,%1,%2,%3}, {%4,%5,%6,%7}, {%8,%9}, {%0,%1,%2,%3};"
        : "+f"(d[0]), "+f"(d[1]), "+f"(d[2]), "+f"(d[3])
        : "r"(a[0]), "r"(a[1]), "r"(a[2]), "r"(a[3]), "r"(b0), "r"(b1));
}
__device__ __forceinline__ void ldsm_x4(uint32_t* r, uint32_t addr) {
    asm volatile("ldmatrix.sync.aligned.m8n8.x4.shared.b16 {%0,%1,%2,%3}, [%4];"
                 : "=r"(r[0]), "=r"(r[1]), "=r"(r[2]), "=r"(r[3]) : "r"(addr));
}
__device__ __forceinline__ void ldsm_x2(uint32_t* r, uint32_t addr) {
    asm volatile("ldmatrix.sync.aligned.m8n8.x2.shared.b16 {%0,%1}, [%2];"
                 : "=r"(r[0]), "=r"(r[1]) : "r"(addr));
}
__device__ __forceinline__ uint32_t smem_u32(const void* p) {
    uint32_t a;
    asm("{ .reg .u64 t; cvta.to.shared.u64 t, %1; cvt.u32.u64 %0, t; }" : "=r"(a) : "l"(p));
    return a;
}

// ---------------- CSR build ----------------
// g_cnt is zero at entry (module-load zero-init; re-zeroed by k_gemm each call).
__global__ void k_count(const int* __restrict__ rows) {
    int e = blockIdx.x * 256 + threadIdx.x;
    if (blockIdx.x == 0 && threadIdx.x < 48) g_flag[threadIdx.x] = 0;
    if (e < NNZ) g_rank[e] = atomicAdd(&g_cnt[rows[e]], 1);
}

// single-pass scan: 48 blocks x 1024, decoupled lookback (all blocks co-resident)
__global__ void k_scan() {
    __shared__ int warp_sums[32];
    __shared__ int prev_total;
    int i = blockIdx.x * 1024 + threadIdx.x;
    int v = g_cnt[i];
    int lane = threadIdx.x & 31, wid = threadIdx.x >> 5;
    if (threadIdx.x == 0) prev_total = 0;
    int x = v;
    #pragma unroll
    for (int o = 1; o < 32; o <<= 1) {
        int y = __shfl_up_sync(0xFFFFFFFFu, x, o);
        if (lane >= o) x += y;
    }
    if (lane == 31) warp_sums[wid] = x;
    __syncthreads();
    if (wid == 0) {
        int s = warp_sums[lane];
        #pragma unroll
        for (int o = 1; o < 32; o <<= 1) {
            int y = __shfl_up_sync(0xFFFFFFFFu, s, o);
            if (lane >= o) s += y;
        }
        warp_sums[lane] = s;
    }
    __syncthreads();
    int excl = x - v + (wid > 0 ? warp_sums[wid - 1] : 0);
    if (threadIdx.x == 1023) {
        g_agg[blockIdx.x] = excl + v;
        __threadfence();
        atomicExch(&g_flag[blockIdx.x], 1);
    }
    if (threadIdx.x < (unsigned)blockIdx.x) {
        while (atomicAdd(&g_flag[threadIdx.x], 0) == 0) {}
        atomicAdd(&prev_total, atomicAdd(&g_agg[threadIdx.x], 0));
    }
    __syncthreads();
    g_rowptr[i] = excl + prev_total;
    if (i == 0) g_rowptr[VV] = NNZ;
}

__global__ void k_scatter(const int* __restrict__ rows, const int* __restrict__ cols,
                          const float* __restrict__ vals) {
    int e = blockIdx.x * 256 + threadIdx.x;
    if (e >= NNZ) return;
    int p = g_rowptr[rows[e]] + g_rank[e];
    g_colidx[p] = cols[e];
    g_vals[p]   = vals[e];
}

// ---------------- half-batch SpMM (batches bo..bo+3), R7-proven ----------------
// Working set of the gather = 4 batches x 12.6MB = 50MB -> L2-resident.
__global__ void k_spmm1h(const float* __restrict__ x, int bo) {  // grid VV, 64 thr
    int v = blockIdx.x;
    int s = g_rowptr[v], e = g_rowptr[v + 1];
    int idx = threadIdx.x * 4;             // 0..255
    int b = bo + (idx >> 6), f = idx & 63;
    const float* src = x + (size_t)b * ((size_t)VV * 64) + f;
    float4 acc = make_float4(0.f, 0.f, 0.f, 0.f);
    for (int j = s; j < e; j++) {
        int c = g_colidx[j];
        float w = g_vals[j];
        float4 t = *(const float4*)(src + (size_t)c * 64);
        acc.x += w * t.x; acc.y += w * t.y; acc.z += w * t.z; acc.w += w * t.w;
    }
    *(float4*)&g_x1[((size_t)b * VV + v) * 64 + f] = acc;
}

__global__ void k_spmm2h(int bo) {                               // grid VV, 64 thr
    int v = blockIdx.x;
    int s = g_rowptr[v], e = g_rowptr[v + 1];
    int idx = threadIdx.x * 4;
    int b = bo + (idx >> 6), f = idx & 63;
    const float* src = g_x1 + (size_t)b * ((size_t)VV * 64) + f;
    float4 acc = make_float4(0.f, 0.f, 0.f, 0.f);
    for (int j = s; j < e; j++) {
        int c = g_colidx[j];
        float w = g_vals[j];
        float4 t = *(const float4*)(src + (size_t)c * 64);
        acc.x += w * t.x; acc.y += w * t.y; acc.z += w * t.z; acc.w += w * t.w;
    }
    *(float4*)&g_xt[((size_t)b * VV + v) * 64 + f] = acc;
}

// ---------------- weight folding + transpose + bf16 split ----------------
__global__ void k_wc(const float* __restrict__ w) {
    int i = blockIdx.x * 256 + threadIdx.x;   // i over FIN*FOUT
    if (i >= FIN * FOUT) return;
    int fi = i >> 6, fo = i & 63;             // fi = K index, fo = N index
    float w0 = w[(fi * 3 + 0) * 64 + fo];
    float w1 = w[(fi * 3 + 1) * 64 + fo];
    float w2 = w[(fi * 3 + 2) * 64 + fo];
    float c[3] = { w0 - w2, w1, 2.0f * w2 };
    #pragma unroll
    for (int s = 0; s < 3; s++) {
        __nv_bfloat16 h = __float2bfloat16(c[s]);
        __nv_bfloat16 l = __float2bfloat16(c[s] - __bfloat162float(h));
        g_wb[(2 * s + 0) * 4096 + fo * 64 + fi] = h;
        g_wb[(2 * s + 1) * 4096 + fo * 64 + fi] = l;
    }
}

// ---------------- mma.sync GEMM: double-buffered A, XOR-swizzled smem ----------------
// out[m][n] = bias[n] + sum_seg sum_k A_seg[m][k] * Wc_seg[k][n]
// bf16 split: out = Ah*Wh + Al*Wh + Ah*Wl (per seg), fp32 accum.
// CTA tile M=128 x N=64, 8 warps (each 16 rows x 64 cols).
// Swizzle: 128B rows, 16B chunk c at (c ^ (row&7))*16 -> no padding, conflict-free.
// A double-buffered: per seg = ldsm(cur) -> STS(next) -> MMA -> 1 sync.

#define SM_BIAS 0                        // 256 B
#define SM_W    256                      // 6 tiles x 8192 B = 49152
#define SM_A0H  (SM_W + 6 * 8192)        // 49408
#define SM_A0L  (SM_A0H + 16384)
#define SM_A1H  (SM_A0L + 16384)
#define SM_A1L  (SM_A1H + 16384)
#define SM_TOT  (SM_A1L + 16384)         // 114944 B (x2 CTAs = 224.5KB <= 228KB)

// convert one float4 (4 consecutive k) to packed bf16 hi/lo and store swizzled
__device__ __forceinline__ void sts_a_hilo(char* sm, int hbase, int lbase,
                                           float4 v, int row, int k4) {
    __nv_bfloat16 h0 = __float2bfloat16(v.x);
    __nv_bfloat16 h1 = __float2bfloat16(v.y);
    __nv_bfloat16 h2 = __float2bfloat16(v.z);
    __nv_bfloat16 h3 = __float2bfloat16(v.w);
    __nv_bfloat16 l0 = __float2bfloat16(v.x - __bfloat162float(h0));
    __nv_bfloat16 l1 = __float2bfloat16(v.y - __bfloat162float(h1));
    __nv_bfloat16 l2 = __float2bfloat16(v.z - __bfloat162float(h2));
    __nv_bfloat16 l3 = __float2bfloat16(v.w - __bfloat162float(h3));
    uint32_t hA = ((uint32_t)__bfloat16_as_ushort(h1) << 16) | __bfloat16_as_ushort(h0);
    uint32_t hB = ((uint32_t)__bfloat16_as_ushort(h3) << 16) | __bfloat16_as_ushort(h2);
    uint32_t lA = ((uint32_t)__bfloat16_as_ushort(l1) << 16) | __bfloat16_as_ushort(l0);
    uint32_t lB = ((uint32_t)__bfloat16_as_ushort(l3) << 16) | __bfloat16_as_ushort(l2);
    int off = row * 128 + (((k4 >> 1) ^ (row & 7)) << 4) + ((k4 & 1) << 3);
    *(uint2*)(sm + hbase + off) = make_uint2(hA, hB);
    *(uint2*)(sm + lbase + off) = make_uint2(lA, lB);
}

__global__ void __launch_bounds__(256, 2) k_gemm(const float* __restrict__ inputs,
                                                 const float* __restrict__ bias,
                                                 float* __restrict__ out) {
    extern __shared__ char sm[];
    float* bias_s = (float*)(sm + SM_BIAS);
    uint32_t smb = smem_u32(sm);
    uint32_t w_u = smb + SM_W;
    uint32_t a_h[2] = { smb + SM_A0H, smb + SM_A1H };
    uint32_t a_l[2] = { smb + SM_A0L, smb + SM_A1L };

    int tid = threadIdx.x;
    int wid = tid >> 5, lane = tid & 31;
    size_t m_base = (size_t)blockIdx.x * 128;

    // restore the g_cnt==0 invariant for the next kernel_launch call
    if (blockIdx.x < 192) g_cnt[blockIdx.x * 256 + tid] = 0;
    if (tid < 64) bias_s[tid] = bias[tid];

    // stage W: 6 bf16 tiles [n=64][k=64], swizzled 128B rows
    {
        const uint32_t* wsrc = (const uint32_t*)g_wb;
        #pragma unroll
        for (int it = 0; it < 48; it++) {
            int p = it * 256 + tid;          // uint32 index, 0..12287
            int t = p >> 11;                 // tile (2048 uint32 per tile)
            int wi = p & 2047;
            int n = wi >> 5, k2 = wi & 31;   // k2 = uint32 within row
            int off = t * 8192 + n * 128 + (((k2 >> 2) ^ (n & 7)) << 4) + ((k2 & 3) << 2);
            *(uint32_t*)(sm + SM_W + off) = wsrc[p];
        }
    }

    const float* seg_src[3] = { inputs + m_base * 64,
                                g_x1 + m_base * 64,
                                g_xt + m_base * 64 };

    // prologue: seg0 -> LDG -> STS(buf0); then LDG seg1 into rv
    float4 rv[8];
    #pragma unroll
    for (int it = 0; it < 8; it++) {
        int g = it * 256 + tid;
        rv[it] = *(const float4*)(seg_src[0] + (size_t)(g >> 4) * 64 + (g & 15) * 4);
    }
    #pragma unroll
    for (int it = 0; it < 8; it++) {
        int g = it * 256 + tid;
        sts_a_hilo(sm, SM_A0H, SM_A0L, rv[it], g >> 4, g & 15);
    }
    __syncthreads();
    #pragma unroll
    for (int it = 0; it < 8; it++) {
        int g = it * 256 + tid;
        rv[it] = *(const float4*)(seg_src[1] + (size_t)(g >> 4) * 64 + (g & 15) * 4);
    }

    float acc[8][4];
    #pragma unroll
    for (int i = 0; i < 8; i++)
        #pragma unroll
        for (int j = 0; j < 4; j++) acc[i][j] = 0.f;

    // A-frag ldsm addressing (swizzled)
    int sel = lane >> 3;                                  // 0..3
    int arow = wid * 16 + (lane & 7) + ((sel & 1) << 3);  // row within tile
    int ar7 = arow & 7;
    int ash = sel >> 1;                                   // 0/1 -> k+0 / k+8 chunk
    uint32_t arow_off = (uint32_t)(arow * 128);
    // B-frag ldsm_x2 addressing (swizzled)
    int bl = lane & 15;
    int bn = bl & 7;
    int bkb = bl >> 3;                                    // 0/1 -> k+0 / k+8 chunk

    #pragma unroll 1
    for (int seg = 0; seg < 3; seg++) {
        int cur = seg & 1;

        // load A fragments (4 k-steps, hi + lo) from current stage
        uint32_t ah[4][4], alo[4][4];
        #pragma unroll
        for (int ks = 0; ks < 4; ks++) {
            uint32_t aoff = arow_off + (uint32_t)((((ks * 2 + ash) ^ ar7)) << 4);
            ldsm_x4(ah[ks], a_h[cur] + aoff);
            ldsm_x4(alo[ks], a_l[cur] + aoff);
        }

        // stage next seg from rv into the other buffers (overlaps MMA below);
        // then (seg0 only) LDG seg2 into rv
        if (seg == 0) {
            #pragma unroll
            for (int it = 0; it < 8; it++) {
                int g = it * 256 + tid;
                sts_a_hilo(sm, SM_A1H, SM_A1L, rv[it], g >> 4, g & 15);
            }
            #pragma unroll
            for (int it = 0; it < 8; it++) {
                int g = it * 256 + tid;
                rv[it] = *(const float4*)(seg_src[2] + (size_t)(g >> 4) * 64 + (g & 15) * 4);
            }
        } else if (seg == 1) {
            #pragma unroll
            for (int it = 0; it < 8; it++) {
                int g = it * 256 + tid;
                sts_a_hilo(sm, SM_A0H, SM_A0L, rv[it], g >> 4, g & 15);
            }
        }

        uint32_t wh_u = w_u + (uint32_t)((seg * 2 + 0) * 8192);
        uint32_t wl_u = w_u + (uint32_t)((seg * 2 + 1) * 8192);

        #pragma unroll
        for (int nt = 0; nt < 8; nt++) {
            uint32_t nrow = (uint32_t)(nt * 1024 + bn * 128);
            #pragma unroll
            for (int ks = 0; ks < 4; ks++) {
                uint32_t boff = nrow + (uint32_t)((((ks * 2 + bkb) ^ bn)) << 4);
                uint32_t bhi[2], blo[2];
                ldsm_x2(bhi, wh_u + boff);
                ldsm_x2(blo, wl_u + boff);
                mma_bf16(acc[nt], ah[ks], bhi[0], bhi[1]);
                mma_bf16(acc[nt], alo[ks], bhi[0], bhi[1]);
                mma_bf16(acc[nt], ah[ks], blo[0], blo[1]);
            }
        }

        if (seg < 2) __syncthreads();
    }

    // epilogue: D frag -> gmem with bias
    int r0 = wid * 16 + (lane >> 2);
    int cb = (lane & 3) * 2;
    float* obase = out + (m_base + r0) * 64;
    #pragma unroll
    for (int nt = 0; nt < 8; nt++) {
        int col = nt * 8 + cb;
        float b0 = bias_s[col], b1 = bias_s[col + 1];
        *(float2*)(obase + col) = make_float2(acc[nt][0] + b0, acc[nt][1] + b1);
        *(float2*)(obase + 8 * 64 + col) = make_float2(acc[nt][2] + b0, acc[nt][3] + b1);
    }
}

// ---------------- launch ----------------
// R7 ordering (best known). k_spmm1h stays at slot 4 (ncu window sentinel).
extern "C" void kernel_launch(void* const* d_in, const int* in_sizes, int n_in,
                              void* d_out, int out_size) {
    const float* inputs  = (const float*)d_in[0];
    const float* weight  = (const float*)d_in[1];
    const float* bias    = (const float*)d_in[2];
    const int*   laprows = (const int*)d_in[3];
    const int*   lapcols = (const int*)d_in[4];
    const float* lapvals = (const float*)d_in[5];
    float* out = (float*)d_out;

    (void)in_sizes; (void)n_in; (void)out_size;

    cudaFuncSetAttribute(k_gemm, cudaFuncAttributeMaxDynamicSharedMemorySize, SM_TOT);

    k_count<<<NNZ / 256, 256>>>(laprows);                      // 1
    k_scan<<<48, 1024>>>();                                    // 2
    k_scatter<<<NNZ / 256, 256>>>(laprows, lapcols, lapvals);  // 3
    k_spmm1h<<<VV, 64>>>(inputs, 0);                           // 4  <- profiled
    k_spmm2h<<<VV, 64>>>(0);                                   // 5
    k_spmm1h<<<VV, 64>>>(inputs, 4);                           // 6
    k_spmm2h<<<VV, 64>>>(4);                                   // 7
    k_wc<<<16, 256>>>(weight);                                 // 8
    k_gemm<<<MM / 128, 256, SM_TOT>>>(inputs, bias, out);      // 9
}

// round 16
// speedup vs baseline: 1.5425x; 1.5425x over previous
#include <cuda_runtime.h>
#include <cuda_bf16.h>
#include <cstdint>

// Problem constants (fixed shapes)
#define BB    8
#define VV    49152
#define FIN   64
#define FOUT  64
#define NNZ   393216
#define MM    (BB * VV)      // 393216 GEMM rows

// ---------------- device scratch (allocation-free) ----------------
__device__ float g_x1[(size_t)MM * 64];   // x1 = L @ x0, layout [B][V][64]
__device__ float g_xt[(size_t)MM * 64];   // t  = L @ x1, layout [B][V][64]
__device__ int   g_cnt[VV];               // invariant: zero at kernel_launch entry
__device__ int   g_rank[NNZ];             // per-edge rank within its row
__device__ int   g_rowptr[VV + 1];
__device__ int   g_agg[48];
__device__ int   g_flag[48];              // zeroed by k_count each call
__device__ int   g_colidx[NNZ];
__device__ float g_vals[NNZ];
// folded + transposed + bf16-split weights: 6 tiles [n=64][k=64]:
// tile 2s = hi(Wc_s^T), tile 2s+1 = lo(Wc_s^T)
__device__ __nv_bfloat16 g_wb[6 * 64 * 64];

// ================= warp MMA helpers (arch-agnostic, sm_80+) =================
__device__ __forceinline__ void mma_bf16(float* d, const uint32_t* a,
                                         uint32_t b0, uint32_t b1) {
    asm volatile(
        "mma.sync.aligned.m16n8k16.row.col.f32.bf16.bf16.f32 "
        "{%0,%1,%2,%3}, {%4,%5,%6,%7}, {%8,%9}, {%0,%1,%2,%3};"
        : "+f"(d[0]), "+f"(d[1]), "+f"(d[2]), "+f"(d[3])
        : "r"(a[0]), "r"(a[1]), "r"(a[2]), "r"(a[3]), "r"(b0), "r"(b1));
}
__device__ __forceinline__ void ldsm_x4(uint32_t* r, uint32_t addr) {
    asm volatile("ldmatrix.sync.aligned.m8n8.x4.shared.b16 {%0,%1,%2,%3}, [%4];"
                 : "=r"(r[0]), "=r"(r[1]), "=r"(r[2]), "=r"(r[3]) : "r"(addr));
}
__device__ __forceinline__ void ldsm_x2(uint32_t* r, uint32_t addr) {
    asm volatile("ldmatrix.sync.aligned.m8n8.x2.shared.b16 {%0,%1}, [%2];"
                 : "=r"(r[0]), "=r"(r[1]) : "r"(addr));
}
__device__ __forceinline__ uint32_t smem_u32(const void* p) {
    uint32_t a;
    asm("{ .reg .u64 t; cvta.to.shared.u64 t, %1; cvt.u32.u64 %0, t; }" : "=r"(a) : "l"(p));
    return a;
}

// ---------------- CSR build (+ fused weight folding) ----------------
// g_cnt is zero at entry (module-load zero-init; re-zeroed by k_gemm each call).
__global__ void k_count(const int* __restrict__ rows, const float* __restrict__ w) {
    int e = blockIdx.x * 256 + threadIdx.x;
    if (blockIdx.x == 0 && threadIdx.x < 48) g_flag[threadIdx.x] = 0;
    // fused weight fold: blocks 1..16 cover FIN*FOUT = 4096 elements
    if (blockIdx.x >= 1 && blockIdx.x <= 16) {
        int i = (blockIdx.x - 1) * 256 + threadIdx.x;
        int fi = i >> 6, fo = i & 63;        // fi = K index, fo = N index
        float w0 = w[(fi * 3 + 0) * 64 + fo];
        float w1 = w[(fi * 3 + 1) * 64 + fo];
        float w2 = w[(fi * 3 + 2) * 64 + fo];
        float c[3] = { w0 - w2, w1, 2.0f * w2 };
        #pragma unroll
        for (int s = 0; s < 3; s++) {
            __nv_bfloat16 h = __float2bfloat16(c[s]);
            __nv_bfloat16 l = __float2bfloat16(c[s] - __bfloat162float(h));
            g_wb[(2 * s + 0) * 4096 + fo * 64 + fi] = h;
            g_wb[(2 * s + 1) * 4096 + fo * 64 + fi] = l;
        }
    }
    if (e < NNZ) g_rank[e] = atomicAdd(&g_cnt[rows[e]], 1);
}

// single-pass scan: 48 blocks x 1024, decoupled lookback (all blocks co-resident)
__global__ void k_scan() {
    __shared__ int warp_sums[32];
    __shared__ int prev_total;
    int i = blockIdx.x * 1024 + threadIdx.x;
    int v = g_cnt[i];
    int lane = threadIdx.x & 31, wid = threadIdx.x >> 5;
    if (threadIdx.x == 0) prev_total = 0;
    int x = v;
    #pragma unroll
    for (int o = 1; o < 32; o <<= 1) {
        int y = __shfl_up_sync(0xFFFFFFFFu, x, o);
        if (lane >= o) x += y;
    }
    if (lane == 31) warp_sums[wid] = x;
    __syncthreads();
    if (wid == 0) {
        int s = warp_sums[lane];
        #pragma unroll
        for (int o = 1; o < 32; o <<= 1) {
            int y = __shfl_up_sync(0xFFFFFFFFu, s, o);
            if (lane >= o) s += y;
        }
        warp_sums[lane] = s;
    }
    __syncthreads();
    int excl = x - v + (wid > 0 ? warp_sums[wid - 1] : 0);
    if (threadIdx.x == 1023) {
        g_agg[blockIdx.x] = excl + v;
        __threadfence();
        atomicExch(&g_flag[blockIdx.x], 1);
    }
    if (threadIdx.x < (unsigned)blockIdx.x) {
        while (atomicAdd(&g_flag[threadIdx.x], 0) == 0) {}
        atomicAdd(&prev_total, atomicAdd(&g_agg[threadIdx.x], 0));
    }
    __syncthreads();
    g_rowptr[i] = excl + prev_total;
    if (i == 0) g_rowptr[VV] = NNZ;
}

__global__ void k_scatter(const int* __restrict__ rows, const int* __restrict__ cols,
                          const float* __restrict__ vals) {
    int e = blockIdx.x * 256 + threadIdx.x;
    if (e >= NNZ) return;
    int p = g_rowptr[rows[e]] + g_rank[e];
    g_colidx[p] = cols[e];
    g_vals[p]   = vals[e];
}

// ---------------- half-batch SpMM (batches bo..bo+3), R7-proven ----------------
// Working set of the gather = 4 batches x 12.6MB = 50MB -> L2-resident.
__global__ void k_spmm1h(const float* __restrict__ x, int bo) {  // grid VV, 64 thr
    int v = blockIdx.x;
    int s = g_rowptr[v], e = g_rowptr[v + 1];
    int idx = threadIdx.x * 4;             // 0..255
    int b = bo + (idx >> 6), f = idx & 63;
    const float* src = x + (size_t)b * ((size_t)VV * 64) + f;
    float4 acc = make_float4(0.f, 0.f, 0.f, 0.f);
    for (int j = s; j < e; j++) {
        int c = g_colidx[j];
        float w = g_vals[j];
        float4 t = *(const float4*)(src + (size_t)c * 64);
        acc.x += w * t.x; acc.y += w * t.y; acc.z += w * t.z; acc.w += w * t.w;
    }
    *(float4*)&g_x1[((size_t)b * VV + v) * 64 + f] = acc;
}

__global__ void k_spmm2h(int bo) {                               // grid VV, 64 thr
    int v = blockIdx.x;
    int s = g_rowptr[v], e = g_rowptr[v + 1];
    int idx = threadIdx.x * 4;
    int b = bo + (idx >> 6), f = idx & 63;
    const float* src = g_x1 + (size_t)b * ((size_t)VV * 64) + f;
    float4 acc = make_float4(0.f, 0.f, 0.f, 0.f);
    for (int j = s; j < e; j++) {
        int c = g_colidx[j];
        float w = g_vals[j];
        float4 t = *(const float4*)(src + (size_t)c * 64);
        acc.x += w * t.x; acc.y += w * t.y; acc.z += w * t.z; acc.w += w * t.w;
    }
    *(float4*)&g_xt[((size_t)b * VV + v) * 64 + f] = acc;
}

// ---------------- mma.sync GEMM (R7: pipelined A, ldsm_x2 B) ----------------
// out[m][n] = bias[n] + sum_seg sum_k A_seg[m][k] * Wc_seg[k][n]
// bf16 split: out = Ah*Wh + Al*Wh + Ah*Wl (per seg), fp32 accum.
// CTA tile M=128 x N=64, 8 warps (each 16 rows x 64 cols).
// Pipeline: per-seg data lives in registers; next seg's LDGs issue before the
// MMA block so DRAM latency overlaps tensor work.

#define WROW 144                       // padded bf16 row stride in bytes (64*2 + 16)
#define SM_BIAS 0                      // 256 B
#define SM_W    256                    // 6 tiles x 64*WROW = 55296
#define SM_AH   (SM_W + 6 * 64 * WROW)
#define SM_AL   (SM_AH + 128 * WROW)
#define SM_TOT  (SM_AL + 128 * WROW)   // 92416 B

__global__ void __launch_bounds__(256, 2) k_gemm(const float* __restrict__ inputs,
                                                 const float* __restrict__ bias,
                                                 float* __restrict__ out) {
    extern __shared__ char sm[];
    float* bias_s = (float*)(sm + SM_BIAS);
    uint32_t smb = smem_u32(sm);
    uint32_t w_u  = smb + SM_W;
    uint32_t ah_u = smb + SM_AH;
    uint32_t al_u = smb + SM_AL;

    int tid = threadIdx.x;
    int wid = tid >> 5, lane = tid & 31;
    size_t m_base = (size_t)blockIdx.x * 128;

    // restore the g_cnt==0 invariant for the next kernel_launch call
    if (blockIdx.x < 192) g_cnt[blockIdx.x * 256 + tid] = 0;
    if (tid < 64) bias_s[tid] = bias[tid];

    // stage W: 6 bf16 tiles [n=64][k=64] -> padded rows, uint4 (16B) granules.
    // 3072 uint4 total; per iter, 8-lane phases write 128 contiguous bytes.
    {
        const uint4* wsrc = (const uint4*)g_wb;
        #pragma unroll
        for (int it = 0; it < 12; it++) {
            int p4 = it * 256 + tid;         // uint4 index, 0..3071
            int t = p4 >> 9;                 // tile (512 uint4 per tile)
            int wi = p4 & 511;
            int n = wi >> 3, c16 = wi & 7;   // row, 16B chunk within row
            *(uint4*)(sm + SM_W + t * (64 * WROW) + n * WROW + c16 * 16) = wsrc[p4];
        }
    }

    float acc[8][4];
    #pragma unroll
    for (int i = 0; i < 8; i++)
        #pragma unroll
        for (int j = 0; j < 4; j++) acc[i][j] = 0.f;

    // per-lane ldmatrix address components
    int sel = lane >> 3;                                  // 0..3
    int arow = wid * 16 + (lane & 7) + ((sel & 1) << 3);  // A row in tile
    uint32_t a_off = (uint32_t)(arow * WROW + ((sel >> 1) << 4));  // +16B for k+8
    int bl = lane & 15;
    int bn = bl & 7;                                      // n within ntile
    uint32_t b_k8 = (uint32_t)(((bl >> 3) << 3) * 2);     // +16B for k+8

    // per-thread staging (8 float4 per thread per seg)
    const float* seg_src[3] = { inputs + m_base * 64,
                                g_x1 + m_base * 64,
                                g_xt + m_base * 64 };

    // prologue: preload seg0 into registers
    float4 rv[8];
    #pragma unroll
    for (int it = 0; it < 8; it++) {
        int g = it * 256 + tid;              // float4 index (0..2047)
        rv[it] = *(const float4*)(seg_src[0] + (size_t)(g >> 4) * 64 + (g & 15) * 4);
    }

    #pragma unroll 1
    for (int seg = 0; seg < 3; seg++) {
        if (seg) __syncthreads();   // previous A frags consumed by all threads

        // convert + STS from registers (hi/lo split)
        #pragma unroll
        for (int it = 0; it < 8; it++) {
            int g = it * 256 + tid;          // float4 index (0..2047)
            int row = g >> 4, k4 = g & 15;
            float4 v = rv[it];
            __nv_bfloat16 h0 = __float2bfloat16(v.x);
            __nv_bfloat16 h1 = __float2bfloat16(v.y);
            __nv_bfloat16 h2 = __float2bfloat16(v.z);
            __nv_bfloat16 h3 = __float2bfloat16(v.w);
            __nv_bfloat16 l0 = __float2bfloat16(v.x - __bfloat162float(h0));
            __nv_bfloat16 l1 = __float2bfloat16(v.y - __bfloat162float(h1));
            __nv_bfloat16 l2 = __float2bfloat16(v.z - __bfloat162float(h2));
            __nv_bfloat16 l3 = __float2bfloat16(v.w - __bfloat162float(h3));
            uint32_t hA = ((uint32_t)__bfloat16_as_ushort(h1) << 16) | __bfloat16_as_ushort(h0);
            uint32_t hB = ((uint32_t)__bfloat16_as_ushort(h3) << 16) | __bfloat16_as_ushort(h2);
            uint32_t lA = ((uint32_t)__bfloat16_as_ushort(l1) << 16) | __bfloat16_as_ushort(l0);
            uint32_t lB = ((uint32_t)__bfloat16_as_ushort(l3) << 16) | __bfloat16_as_ushort(l2);
            int off = row * WROW + k4 * 8;
            *(uint2*)(sm + SM_AH + off) = make_uint2(hA, hB);
            *(uint2*)(sm + SM_AL + off) = make_uint2(lA, lB);
        }
        __syncthreads();

        // prefetch next segment's A tile into registers (overlaps MMA below)
        if (seg < 2) {
            const float* nsrc = seg_src[seg + 1];
            #pragma unroll
            for (int it = 0; it < 8; it++) {
                int g = it * 256 + tid;
                rv[it] = *(const float4*)(nsrc + (size_t)(g >> 4) * 64 + (g & 15) * 4);
            }
        }

        // load A fragments (4 k-steps, hi + lo)
        uint32_t ah[4][4], alo[4][4];
        #pragma unroll
        for (int ks = 0; ks < 4; ks++) ldsm_x4(ah[ks], ah_u + a_off + ks * 32);
        #pragma unroll
        for (int ks = 0; ks < 4; ks++) ldsm_x4(alo[ks], al_u + a_off + ks * 32);

        uint32_t wh_u = w_u + (seg * 2 + 0) * (64 * WROW);
        uint32_t wl_u = w_u + (seg * 2 + 1) * (64 * WROW);

        #pragma unroll
        for (int nt = 0; nt < 8; nt++) {
            uint32_t nrow_off = (uint32_t)((nt * 8 + bn) * WROW) + b_k8;
            #pragma unroll
            for (int ks = 0; ks < 4; ks++) {
                uint32_t bhi[2], blo[2];
                uint32_t boff = nrow_off + (uint32_t)(ks * 32);
                ldsm_x2(bhi, wh_u + boff);
                ldsm_x2(blo, wl_u + boff);
                mma_bf16(acc[nt], ah[ks], bhi[0], bhi[1]);
                mma_bf16(acc[nt], alo[ks], bhi[0], bhi[1]);
                mma_bf16(acc[nt], ah[ks], blo[0], blo[1]);
            }
        }
    }

    // epilogue: D frag -> gmem with bias
    int r0 = wid * 16 + (lane >> 2);
    int cb = (lane & 3) * 2;
    float* obase = out + (m_base + r0) * 64;
    #pragma unroll
    for (int nt = 0; nt < 8; nt++) {
        int col = nt * 8 + cb;
        float b0 = bias_s[col], b1 = bias_s[col + 1];
        *(float2*)(obase + col) = make_float2(acc[nt][0] + b0, acc[nt][1] + b1);
        *(float2*)(obase + 8 * 64 + col) = make_float2(acc[nt][2] + b0, acc[nt][3] + b1);
    }
}

// ---------------- launch ----------------
// R7 ordering (best known). k_spmm1h stays at slot 4 (ncu window sentinel).
extern "C" void kernel_launch(void* const* d_in, const int* in_sizes, int n_in,
                              void* d_out, int out_size) {
    const float* inputs  = (const float*)d_in[0];
    const float* weight  = (const float*)d_in[1];
    const float* bias    = (const float*)d_in[2];
    const int*   laprows = (const int*)d_in[3];
    const int*   lapcols = (const int*)d_in[4];
    const float* lapvals = (const float*)d_in[5];
    float* out = (float*)d_out;

    (void)in_sizes; (void)n_in; (void)out_size;

    cudaFuncSetAttribute(k_gemm, cudaFuncAttributeMaxDynamicSharedMemorySize, SM_TOT);

    k_count<<<NNZ / 256, 256>>>(laprows, weight);              // 1 (+ weight fold)
    k_scan<<<48, 1024>>>();                                    // 2
    k_scatter<<<NNZ / 256, 256>>>(laprows, lapcols, lapvals);  // 3
    k_spmm1h<<<VV, 64>>>(inputs, 0);                           // 4  <- profiled
    k_spmm2h<<<VV, 64>>>(0);                                   // 5
    k_spmm1h<<<VV, 64>>>(inputs, 4);                           // 6
    k_spmm2h<<<VV, 64>>>(4);                                   // 7
    k_gemm<<<MM / 128, 256, SM_TOT>>>(inputs, bias, out);      // 8
}

// round 17
// speedup vs baseline: 1.7627x; 1.1428x over previous
#include <cuda_runtime.h>
#include <cuda_bf16.h>
#include <cstdint>

// Problem constants (fixed shapes)
#define BB    8
#define VV    49152
#define FIN   64
#define FOUT  64
#define NNZ   393216
#define MM    (BB * VV)      // 393216 GEMM rows

// ---------------- device scratch (allocation-free) ----------------
__device__ __nv_bfloat16 g_x1b[(size_t)MM * 64];  // x1 = L @ x0 (bf16), [B][V][64]
__device__ __nv_bfloat16 g_xtb[(size_t)MM * 64];  // t  = L @ x1 (bf16), [B][V][64]
__device__ int   g_cnt[VV];               // invariant: zero at kernel_launch entry
__device__ int   g_rank[NNZ];             // per-edge rank within its row
__device__ int   g_rowptr[VV + 1];
__device__ int   g_agg[48];
__device__ int   g_flag[48];              // zeroed by k_count each call
__device__ int   g_colidx[NNZ];
__device__ float g_vals[NNZ];
// folded + transposed + bf16-split weights: 6 tiles [n=64][k=64]:
// tile 2s = hi(Wc_s^T), tile 2s+1 = lo(Wc_s^T)
__device__ __nv_bfloat16 g_wb[6 * 64 * 64];

// ================= warp MMA helpers (arch-agnostic, sm_80+) =================
__device__ __forceinline__ void mma_bf16(float* d, const uint32_t* a,
                                         uint32_t b0, uint32_t b1) {
    asm volatile(
        "mma.sync.aligned.m16n8k16.row.col.f32.bf16.bf16.f32 "
        "{%0,%1,%2,%3}, {%4,%5,%6,%7}, {%8,%9}, {%0,%1,%2,%3};"
        : "+f"(d[0]), "+f"(d[1]), "+f"(d[2]), "+f"(d[3])
        : "r"(a[0]), "r"(a[1]), "r"(a[2]), "r"(a[3]), "r"(b0), "r"(b1));
}
__device__ __forceinline__ void ldsm_x4(uint32_t* r, uint32_t addr) {
    asm volatile("ldmatrix.sync.aligned.m8n8.x4.shared.b16 {%0,%1,%2,%3}, [%4];"
                 : "=r"(r[0]), "=r"(r[1]), "=r"(r[2]), "=r"(r[3]) : "r"(addr));
}
__device__ __forceinline__ void ldsm_x2(uint32_t* r, uint32_t addr) {
    asm volatile("ldmatrix.sync.aligned.m8n8.x2.shared.b16 {%0,%1}, [%2];"
                 : "=r"(r[0]), "=r"(r[1]) : "r"(addr));
}
__device__ __forceinline__ uint32_t smem_u32(const void* p) {
    uint32_t a;
    asm("{ .reg .u64 t; cvta.to.shared.u64 t, %1; cvt.u32.u64 %0, t; }" : "=r"(a) : "l"(p));
    return a;
}
__device__ __forceinline__ uint32_t pack_bf16x2(float x, float y) {
    return ((uint32_t)__bfloat16_as_ushort(__float2bfloat16(y)) << 16) |
           __bfloat16_as_ushort(__float2bfloat16(x));
}

// ---------------- CSR build (+ fused weight folding) ----------------
// g_cnt is zero at entry (module-load zero-init; re-zeroed by k_gemm each call).
__global__ void k_count(const int* __restrict__ rows, const float* __restrict__ w) {
    int e = blockIdx.x * 256 + threadIdx.x;
    if (blockIdx.x == 0 && threadIdx.x < 48) g_flag[threadIdx.x] = 0;
    // fused weight fold: blocks 1..16 cover FIN*FOUT = 4096 elements
    if (blockIdx.x >= 1 && blockIdx.x <= 16) {
        int i = (blockIdx.x - 1) * 256 + threadIdx.x;
        int fi = i >> 6, fo = i & 63;        // fi = K index, fo = N index
        float w0 = w[(fi * 3 + 0) * 64 + fo];
        float w1 = w[(fi * 3 + 1) * 64 + fo];
        float w2 = w[(fi * 3 + 2) * 64 + fo];
        float c[3] = { w0 - w2, w1, 2.0f * w2 };
        #pragma unroll
        for (int s = 0; s < 3; s++) {
            __nv_bfloat16 h = __float2bfloat16(c[s]);
            __nv_bfloat16 l = __float2bfloat16(c[s] - __bfloat162float(h));
            g_wb[(2 * s + 0) * 4096 + fo * 64 + fi] = h;
            g_wb[(2 * s + 1) * 4096 + fo * 64 + fi] = l;
        }
    }
    if (e < NNZ) g_rank[e] = atomicAdd(&g_cnt[rows[e]], 1);
}

// single-pass scan: 48 blocks x 1024, decoupled lookback (all blocks co-resident)
__global__ void k_scan() {
    __shared__ int warp_sums[32];
    __shared__ int prev_total;
    int i = blockIdx.x * 1024 + threadIdx.x;
    int v = g_cnt[i];
    int lane = threadIdx.x & 31, wid = threadIdx.x >> 5;
    if (threadIdx.x == 0) prev_total = 0;
    int x = v;
    #pragma unroll
    for (int o = 1; o < 32; o <<= 1) {
        int y = __shfl_up_sync(0xFFFFFFFFu, x, o);
        if (lane >= o) x += y;
    }
    if (lane == 31) warp_sums[wid] = x;
    __syncthreads();
    if (wid == 0) {
        int s = warp_sums[lane];
        #pragma unroll
        for (int o = 1; o < 32; o <<= 1) {
            int y = __shfl_up_sync(0xFFFFFFFFu, s, o);
            if (lane >= o) s += y;
        }
        warp_sums[lane] = s;
    }
    __syncthreads();
    int excl = x - v + (wid > 0 ? warp_sums[wid - 1] : 0);
    if (threadIdx.x == 1023) {
        g_agg[blockIdx.x] = excl + v;
        __threadfence();
        atomicExch(&g_flag[blockIdx.x], 1);
    }
    if (threadIdx.x < (unsigned)blockIdx.x) {
        while (atomicAdd(&g_flag[threadIdx.x], 0) == 0) {}
        atomicAdd(&prev_total, atomicAdd(&g_agg[threadIdx.x], 0));
    }
    __syncthreads();
    g_rowptr[i] = excl + prev_total;
    if (i == 0) g_rowptr[VV] = NNZ;
}

__global__ void k_scatter(const int* __restrict__ rows, const int* __restrict__ cols,
                          const float* __restrict__ vals) {
    int e = blockIdx.x * 256 + threadIdx.x;
    if (e >= NNZ) return;
    int p = g_rowptr[rows[e]] + g_rank[e];
    g_colidx[p] = cols[e];
    g_vals[p]   = vals[e];
}

// ---------------- half-batch SpMM (batches bo..bo+3) ----------------
// spmm1: gather fp32 inputs (1KB/edge), write bf16 x1 (halved writes).
__global__ void k_spmm1h(const float* __restrict__ x, int bo) {  // grid VV, 64 thr
    int v = blockIdx.x;
    int s = g_rowptr[v], e = g_rowptr[v + 1];
    int idx = threadIdx.x * 4;             // 0..255
    int b = bo + (idx >> 6), f = idx & 63;
    const float* src = x + (size_t)b * ((size_t)VV * 64) + f;
    float4 acc = make_float4(0.f, 0.f, 0.f, 0.f);
    for (int j = s; j < e; j++) {
        int c = g_colidx[j];
        float w = g_vals[j];
        float4 t = *(const float4*)(src + (size_t)c * 64);
        acc.x += w * t.x; acc.y += w * t.y; acc.z += w * t.z; acc.w += w * t.w;
    }
    *(uint2*)&g_x1b[((size_t)b * VV + v) * 64 + f] =
        make_uint2(pack_bf16x2(acc.x, acc.y), pack_bf16x2(acc.z, acc.w));
}

// spmm2: gather bf16 x1 (512B/edge — halved gather traffic), write bf16 xt.
__global__ void k_spmm2h(int bo) {                               // grid VV, 64 thr
    int v = blockIdx.x;
    int s = g_rowptr[v], e = g_rowptr[v + 1];
    int idx = threadIdx.x * 4;
    int b = bo + (idx >> 6), f = idx & 63;
    const __nv_bfloat16* src = g_x1b + (size_t)b * ((size_t)VV * 64) + f;
    float4 acc = make_float4(0.f, 0.f, 0.f, 0.f);
    for (int j = s; j < e; j++) {
        int c = g_colidx[j];
        float w = g_vals[j];
        uint2 raw = *(const uint2*)(src + (size_t)c * 64);
        __nv_bfloat162 pa = *reinterpret_cast<__nv_bfloat162*>(&raw.x);
        __nv_bfloat162 pb = *reinterpret_cast<__nv_bfloat162*>(&raw.y);
        float2 fa = __bfloat1622float2(pa);
        float2 fb = __bfloat1622float2(pb);
        acc.x += w * fa.x; acc.y += w * fa.y; acc.z += w * fb.x; acc.w += w * fb.y;
    }
    *(uint2*)&g_xtb[((size_t)b * VV + v) * 64 + f] =
        make_uint2(pack_bf16x2(acc.x, acc.y), pack_bf16x2(acc.z, acc.w));
}

// ---------------- mma.sync GEMM ----------------
// out[m][n] = bias[n] + x0*Wc0 + x1*Wc1 + t*Wc2
// seg0 (x0, fp32): hi/lo split, 3 MMA passes (Ah*Wh + Al*Wh + Ah*Wl).
// seg1/2 (x1/xt, bf16 in gmem): raw uint4 copy to smem, 2 passes (Ah*Wh + Ah*Wl).
// CTA tile M=128 x N=64, 8 warps (each 16 rows x 64 cols).

#define WROW 144                       // padded bf16 row stride in bytes (64*2 + 16)
#define SM_BIAS 0                      // 256 B
#define SM_W    256                    // 6 tiles x 64*WROW = 55296
#define SM_AH   (SM_W + 6 * 64 * WROW)
#define SM_AL   (SM_AH + 128 * WROW)
#define SM_TOT  (SM_AL + 128 * WROW)   // 92416 B

__global__ void __launch_bounds__(256, 2) k_gemm(const float* __restrict__ inputs,
                                                 const float* __restrict__ bias,
                                                 float* __restrict__ out) {
    extern __shared__ char sm[];
    float* bias_s = (float*)(sm + SM_BIAS);
    uint32_t smb = smem_u32(sm);
    uint32_t w_u  = smb + SM_W;
    uint32_t ah_u = smb + SM_AH;
    uint32_t al_u = smb + SM_AL;

    int tid = threadIdx.x;
    int wid = tid >> 5, lane = tid & 31;
    size_t m_base = (size_t)blockIdx.x * 128;

    // restore the g_cnt==0 invariant for the next kernel_launch call
    if (blockIdx.x < 192) g_cnt[blockIdx.x * 256 + tid] = 0;
    if (tid < 64) bias_s[tid] = bias[tid];

    // stage W: 6 bf16 tiles [n=64][k=64] -> padded rows, uint4 granules
    {
        const uint4* wsrc = (const uint4*)g_wb;
        #pragma unroll
        for (int it = 0; it < 12; it++) {
            int p4 = it * 256 + tid;         // uint4 index, 0..3071
            int t = p4 >> 9;                 // tile (512 uint4 per tile)
            int wi = p4 & 511;
            int n = wi >> 3, c16 = wi & 7;   // row, 16B chunk within row
            *(uint4*)(sm + SM_W + t * (64 * WROW) + n * WROW + c16 * 16) = wsrc[p4];
        }
    }

    float acc[8][4];
    #pragma unroll
    for (int i = 0; i < 8; i++)
        #pragma unroll
        for (int j = 0; j < 4; j++) acc[i][j] = 0.f;

    // per-lane ldmatrix address components
    int sel = lane >> 3;                                  // 0..3
    int arow = wid * 16 + (lane & 7) + ((sel & 1) << 3);  // A row in tile
    uint32_t a_off = (uint32_t)(arow * WROW + ((sel >> 1) << 4));  // +16B for k+8
    int bl = lane & 15;
    int bn = bl & 7;                                      // n within ntile
    uint32_t b_k8 = (uint32_t)(((bl >> 3) << 3) * 2);     // +16B for k+8

    // prologue: preload seg0 (fp32 inputs) into registers
    const float* src0 = inputs + m_base * 64;
    float4 rv[8];
    #pragma unroll
    for (int it = 0; it < 8; it++) {
        int g = it * 256 + tid;              // float4 index (0..2047)
        rv[it] = *(const float4*)(src0 + (size_t)(g >> 4) * 64 + (g & 15) * 4);
    }

    // ======== seg0: fp32 hi/lo, 3 passes ========
    #pragma unroll
    for (int it = 0; it < 8; it++) {
        int g = it * 256 + tid;
        int row = g >> 4, k4 = g & 15;
        float4 v = rv[it];
        __nv_bfloat16 h0 = __float2bfloat16(v.x);
        __nv_bfloat16 h1 = __float2bfloat16(v.y);
        __nv_bfloat16 h2 = __float2bfloat16(v.z);
        __nv_bfloat16 h3 = __float2bfloat16(v.w);
        uint32_t hA = ((uint32_t)__bfloat16_as_ushort(h1) << 16) | __bfloat16_as_ushort(h0);
        uint32_t hB = ((uint32_t)__bfloat16_as_ushort(h3) << 16) | __bfloat16_as_ushort(h2);
        uint32_t lA = pack_bf16x2(v.x - __bfloat162float(h0), v.y - __bfloat162float(h1));
        uint32_t lB = pack_bf16x2(v.z - __bfloat162float(h2), v.w - __bfloat162float(h3));
        int off = row * WROW + k4 * 8;
        *(uint2*)(sm + SM_AH + off) = make_uint2(hA, hB);
        *(uint2*)(sm + SM_AL + off) = make_uint2(lA, lB);
    }
    __syncthreads();

    // prefetch seg1 (bf16 x1 tile, 16KB) into registers
    uint4 rb[4];
    {
        const uint4* nb = (const uint4*)(g_x1b + m_base * 64);
        #pragma unroll
        for (int it = 0; it < 4; it++) rb[it] = nb[it * 256 + tid];
    }

    {
        uint32_t ah[4][4], alo[4][4];
        #pragma unroll
        for (int ks = 0; ks < 4; ks++) ldsm_x4(ah[ks], ah_u + a_off + ks * 32);
        #pragma unroll
        for (int ks = 0; ks < 4; ks++) ldsm_x4(alo[ks], al_u + a_off + ks * 32);

        uint32_t wh_u = w_u + 0 * (64 * WROW);
        uint32_t wl_u = w_u + 1 * (64 * WROW);
        #pragma unroll
        for (int nt = 0; nt < 8; nt++) {
            uint32_t nrow_off = (uint32_t)((nt * 8 + bn) * WROW) + b_k8;
            #pragma unroll
            for (int ks = 0; ks < 4; ks++) {
                uint32_t bhi[2], blo[2];
                uint32_t boff = nrow_off + (uint32_t)(ks * 32);
                ldsm_x2(bhi, wh_u + boff);
                ldsm_x2(blo, wl_u + boff);
                mma_bf16(acc[nt], ah[ks], bhi[0], bhi[1]);
                mma_bf16(acc[nt], alo[ks], bhi[0], bhi[1]);
                mma_bf16(acc[nt], ah[ks], blo[0], blo[1]);
            }
        }
    }

    // ======== seg1 / seg2: bf16 A, 2 passes ========
    #pragma unroll 1
    for (int seg = 1; seg < 3; seg++) {
        __syncthreads();   // previous A frags consumed by all warps

        // stage bf16 tile from rb (raw copy, no conversion)
        #pragma unroll
        for (int it = 0; it < 4; it++) {
            int g = it * 256 + tid;          // uint4 index (0..1023)
            int row = g >> 3, c16 = g & 7;
            *(uint4*)(sm + SM_AH + row * WROW + c16 * 16) = rb[it];
        }
        __syncthreads();

        // prefetch seg2 tile (overlaps MMA below)
        if (seg == 1) {
            const uint4* nb = (const uint4*)(g_xtb + m_base * 64);
            #pragma unroll
            for (int it = 0; it < 4; it++) rb[it] = nb[it * 256 + tid];
        }

        uint32_t ah[4][4];
        #pragma unroll
        for (int ks = 0; ks < 4; ks++) ldsm_x4(ah[ks], ah_u + a_off + ks * 32);

        uint32_t wh_u = w_u + (seg * 2 + 0) * (64 * WROW);
        uint32_t wl_u = w_u + (seg * 2 + 1) * (64 * WROW);
        #pragma unroll
        for (int nt = 0; nt < 8; nt++) {
            uint32_t nrow_off = (uint32_t)((nt * 8 + bn) * WROW) + b_k8;
            #pragma unroll
            for (int ks = 0; ks < 4; ks++) {
                uint32_t bhi[2], blo[2];
                uint32_t boff = nrow_off + (uint32_t)(ks * 32);
                ldsm_x2(bhi, wh_u + boff);
                ldsm_x2(blo, wl_u + boff);
                mma_bf16(acc[nt], ah[ks], bhi[0], bhi[1]);
                mma_bf16(acc[nt], ah[ks], blo[0], blo[1]);
            }
        }
    }

    // epilogue: D frag -> gmem with bias
    int r0 = wid * 16 + (lane >> 2);
    int cb = (lane & 3) * 2;
    float* obase = out + (m_base + r0) * 64;
    #pragma unroll
    for (int nt = 0; nt < 8; nt++) {
        int col = nt * 8 + cb;
        float b0 = bias_s[col], b1 = bias_s[col + 1];
        *(float2*)(obase + col) = make_float2(acc[nt][0] + b0, acc[nt][1] + b1);
        *(float2*)(obase + 8 * 64 + col) = make_float2(acc[nt][2] + b0, acc[nt][3] + b1);
    }
}

// ---------------- launch ----------------
// R7 ordering (best known). k_spmm1h stays at slot 4 (ncu window sentinel).
extern "C" void kernel_launch(void* const* d_in, const int* in_sizes, int n_in,
                              void* d_out, int out_size) {
    const float* inputs  = (const float*)d_in[0];
    const float* weight  = (const float*)d_in[1];
    const float* bias    = (const float*)d_in[2];
    const int*   laprows = (const int*)d_in[3];
    const int*   lapcols = (const int*)d_in[4];
    const float* lapvals = (const float*)d_in[5];
    float* out = (float*)d_out;

    (void)in_sizes; (void)n_in; (void)out_size;

    cudaFuncSetAttribute(k_gemm, cudaFuncAttributeMaxDynamicSharedMemorySize, SM_TOT);

    k_count<<<NNZ / 256, 256>>>(laprows, weight);              // 1 (+ weight fold)
    k_scan<<<48, 1024>>>();                                    // 2
    k_scatter<<<NNZ / 256, 256>>>(laprows, lapcols, lapvals);  // 3
    k_spmm1h<<<VV, 64>>>(inputs, 0);                           // 4  <- profiled
    k_spmm2h<<<VV, 64>>>(0);                                   // 5
    k_spmm1h<<<VV, 64>>>(inputs, 4);                           // 6
    k_spmm2h<<<VV, 64>>>(4);                                   // 7
    k_gemm<<<MM / 128, 256, SM_TOT>>>(inputs, bias, out);      // 8
}